// round 12
// baseline (speedup 1.0000x reference)
#include <cuda_runtime.h>
#include <cuda_bf16.h>
#include <mma.h>
#include <math.h>
#include <cstdint>

using namespace nvcuda;

// Problem constants
#define NN 50000
#define EE 800000
#define HH 4
#define FF 64
#define CC 256   // H*F == CIN
#define CAPW 64  // per-warp cached degree; fallback to global beyond

// ---------------- device scratch (static, no allocation) ----------------
__device__ float    g_xcomb [(size_t)NN*CC];
__device__ float    g_xl    [(size_t)NN*CC];
__device__ float    g_xr    [(size_t)NN*CC];
__device__ float    g_ident [(size_t)NN*CC];
__device__ float    g_pre   [(size_t)NN*CC];
__device__ float    g_logits[(size_t)EE*HH];   // high-degree fallback (CSR-slot indexed)
__device__ float    g_nuv   [(size_t)NN*2];
__device__ float    g_w2t   [32*64];           // transposed pe_w2
__device__ float    g_wr    [4*CC*CC];         // tf32-rounded weights: lin_l, lin_r, res, proj
__device__ int      g_deg   [NN+1];
__device__ int      g_off   [NN+1];
__device__ int      g_cursor[NN+1];
__device__ int      g_csr   [EE];

// ---------------- helpers ----------------
__device__ __forceinline__ float wsum(float v){
#pragma unroll
    for (int o=16;o>0;o>>=1) v += __shfl_xor_sync(0xffffffffu, v, o);
    return v;
}

__device__ __forceinline__ float rtf32(float x){
    return wmma::__float_to_tf32(x);
}

__device__ __forceinline__ void cp_async16(unsigned int dst, const float* src, bool full){
    if (full)
        asm volatile("cp.async.cg.shared.global [%0], [%1], 16;" :: "r"(dst), "l"(src));
    else
        asm volatile("cp.async.cg.shared.global [%0], [%1], 16, 0;" :: "r"(dst), "l"(src));
}

// ---------------- kernels ----------------
// nuv precompute + degree zeroing (runs FIRST; enables the parallel edge chain)
__global__ void k_nuv(const float* __restrict__ kpts){
    int i = blockIdx.x*blockDim.x + threadIdx.x;
    if (i < NN){
        g_nuv[i*2+0] = kpts[i*2+0] * (1.f/1216.f);
        g_nuv[i*2+1] = kpts[i*2+1] * (1.f/352.f);
    }
    if (i < NN+1) g_deg[i] = 0;
}

// transpose pe_w2 (64x32 -> 32x64) for coalesced reads in k_pos
__global__ void k_prep(const float* __restrict__ w2){
    for (int idx=threadIdx.x; idx<2048; idx+=blockDim.x){
        int k = idx >> 6, c = idx & 63;
        g_w2t[idx] = w2[c*32 + k];
    }
}

// round the 4 GEMM weight matrices to tf32 once
__global__ void k_roundw(const float* __restrict__ w0, const float* __restrict__ w1,
                         const float* __restrict__ w2, const float* __restrict__ w3){
    int i = blockIdx.x*blockDim.x + threadIdx.x;
    if (i >= CC*CC) return;
    g_wr[i]           = rtf32(w0[i]);
    g_wr[CC*CC + i]   = rtf32(w1[i]);
    g_wr[2*CC*CC + i] = rtf32(w2[i]);
    g_wr[3*CC*CC + i] = rtf32(w3[i]);
}

// positional encoder + build x_comb (tf32-rounded). One warp per node.
__global__ void k_pos(const float* __restrict__ x, const float* __restrict__ kpts,
                      const float* __restrict__ pts,
                      const float* __restrict__ w1, const float* __restrict__ b1,
                      const float* __restrict__ g1, const float* __restrict__ bn1,
                      const float* __restrict__ b2,
                      const float* __restrict__ g2, const float* __restrict__ bn2)
{
    int node = (blockIdx.x*blockDim.x + threadIdx.x) >> 5;
    int lane = threadIdx.x & 31;
    if (node >= NN) return;
    float u  = kpts[node*2+0] * (1.f/1216.f);
    float v  = kpts[node*2+1] * (1.f/352.f);
    float dep = fminf(fmaxf(pts[node*3+2], 0.1f), 100.f);

    float a = w1[lane*3+0]*u + w1[lane*3+1]*v + w1[lane*3+2]*dep + b1[lane];
    float m = wsum(a) * (1.f/32.f);
    float d0 = a - m;
    float var = wsum(d0*d0) * (1.f/32.f);
    float hn = d0 * rsqrtf(var + 1e-5f) * g1[lane] + bn1[lane];
    float h = hn / (1.f + expf(-hn));

    float acc0 = b2[lane], acc1 = b2[lane+32];
#pragma unroll
    for (int k=0;k<32;k++){
        float hk = __shfl_sync(0xffffffffu, h, k);
        acc0 += hk * g_w2t[k*64 + lane];
        acc1 += hk * g_w2t[k*64 + 32 + lane];
    }
    float m2 = wsum(acc0 + acc1) * (1.f/64.f);
    float e0 = acc0 - m2, e1 = acc1 - m2;
    float var2 = wsum(e0*e0 + e1*e1) * (1.f/64.f);
    float rs = rsqrtf(var2 + 1e-5f);
    float p0 = e0*rs*g2[lane]    + bn2[lane];
    float p1 = e1*rs*g2[lane+32] + bn2[lane+32];

    size_t base = (size_t)node * CC;
    g_xcomb[base + 192 + lane] = rtf32(p0);
    g_xcomb[base + 224 + lane] = rtf32(p1);
#pragma unroll
    for (int j=lane; j<192; j+=32) g_xcomb[base + j] = rtf32(x[(size_t)node*192 + j]);
}

// ---------------- tf32 tensor-core GEMM, 128x128 tile, cp.async 2-stage ----------------
#define SS (128*40)                 // floats per matrix per stage
#define GEMM_SMEM (2*2*SS*4)        // 81920 B (also covers Cs 128*136*4 = 69632)

__global__ void __launch_bounds__(256, 2)
k_tcgemm2(const float* __restrict__ A,
          const float* __restrict__ Wbase, int tgt0,
          const float* __restrict__ b0, const float* __restrict__ b1,
          const float* __restrict__ b2,
          float* __restrict__ C0, float* __restrict__ C1,
          float* __restrict__ C2, int M)
{
    extern __shared__ float sm[];

    int t  = threadIdx.x;
    int m0 = blockIdx.x * 128;
    int tgt = blockIdx.y >> 1;
    int c0  = (blockIdx.y & 1) * 128;

    const float* W    = Wbase + (size_t)(tgt0 + tgt)*CC*CC;
    const float* bias = (tgt == 0) ? b0 : (tgt == 1) ? b1 : b2;
    float*       C    = (tgt == 0) ? C0 : (tgt == 1) ? C1 : C2;

    int warp = t >> 5;
    int r  = (warp & 3) * 32;
    int cb = (warp >> 2) * 64;

    unsigned int smb = (unsigned int)__cvta_generic_to_shared(sm);

    int rows[4], cols[4];
#pragma unroll
    for (int j=0;j<4;j++){
        int id = t + j*256;
        rows[j] = id >> 3;
        cols[j] = (id & 7) * 4;
    }

    wmma::fragment<wmma::accumulator, 16, 16, 8, float> acc[2][4];
#pragma unroll
    for (int i=0;i<2;i++)
#pragma unroll
        for (int j=0;j<4;j++) wmma::fill_fragment(acc[i][j], 0.f);

    auto issue = [&](int k0, int s){
#pragma unroll
        for (int j=0;j<4;j++){
            int row = rows[j], col = cols[j];
            bool vA = (m0 + row < M);
            const float* srcA = &A[(size_t)((vA ? m0 + row : 0)) * CC + k0 + col];
            cp_async16(smb + (unsigned int)((s*2*SS + row*40 + col)*4), srcA, vA);
            const float* srcW = &W[(size_t)(c0 + row) * CC + k0 + col];
            cp_async16(smb + (unsigned int)((s*2*SS + SS + row*40 + col)*4), srcW, true);
        }
        asm volatile("cp.async.commit_group;" ::: "memory");
    };

    issue(0, 0);

    for (int it = 0; it < 8; ++it){
        int s = it & 1;
        if (it < 7) issue((it+1)*32, s^1);
        if (it < 7) asm volatile("cp.async.wait_group 1;" ::: "memory");
        else        asm volatile("cp.async.wait_group 0;" ::: "memory");
        __syncthreads();

        float* As = sm + s*2*SS;
        float* Ws = As + SS;
#pragma unroll
        for (int kk = 0; kk < 32; kk += 8){
            wmma::fragment<wmma::matrix_a, 16, 16, 8, wmma::precision::tf32, wmma::row_major> af[2];
            wmma::fragment<wmma::matrix_b, 16, 16, 8, wmma::precision::tf32, wmma::col_major> bf[4];
#pragma unroll
            for (int i = 0; i < 2; i++)
                wmma::load_matrix_sync(af[i], &As[(r + 16*i)*40 + kk], 40);
#pragma unroll
            for (int j = 0; j < 4; j++)
                wmma::load_matrix_sync(bf[j], &Ws[(cb + 16*j)*40 + kk], 40);
#pragma unroll
            for (int i = 0; i < 2; i++)
#pragma unroll
                for (int j = 0; j < 4; j++)
                    wmma::mma_sync(acc[i][j], af[i], bf[j], acc[i][j]);
        }
        __syncthreads();
    }

    float* Cs = sm;  // [128][136] aliases both stages
#pragma unroll
    for (int i = 0; i < 2; i++)
#pragma unroll
        for (int j = 0; j < 4; j++)
            wmma::store_matrix_sync(&Cs[(r + 16*i)*136 + cb + 16*j], acc[i][j], 136, wmma::mem_row_major);
    __syncthreads();

    int col4 = (t & 31) * 4;
    int rb   = t >> 5;
    float4 bv = *(const float4*)&bias[c0 + col4];
#pragma unroll
    for (int i = 0; i < 16; i++){
        int row = rb + i * 8;
        int m = m0 + row;
        if (m < M){
            float4 v = *(float4*)&Cs[row*136 + col4];
            v.x += bv.x; v.y += bv.y; v.z += bv.z; v.w += bv.w;
            *(float4*)&C[(size_t)m * CC + c0 + col4] = v;
        }
    }
}

// edge_attr output + degree histogram
__global__ void k_edgeattr(const int* __restrict__ ei, float* __restrict__ ea)
{
    int e = blockIdx.x*blockDim.x + threadIdx.x;
    if (e >= EE) return;
    int s = ei[e], d = ei[EE + e];
    float r0 = g_nuv[d*2+0] - g_nuv[s*2+0];
    float r1 = g_nuv[d*2+1] - g_nuv[s*2+1];
    float dist = sqrtf(r0*r0 + r1*r1);
    ea[(size_t)e*3+0] = r0;
    ea[(size_t)e*3+1] = r1;
    ea[(size_t)e*3+2] = dist;
    atomicAdd(&g_deg[d], 1);
}

// single-block exclusive scan of degrees -> offsets (+cursor copy)
__global__ void k_scan()
{
    __shared__ int warpsum[32];
    __shared__ int warpoff[32];
    int t = threadIdx.x;
    int lane = t & 31, wid = t >> 5;
    int carry = 0;
    for (int base = 0; base < NN; base += 1024){
        int v = (base + t < NN) ? g_deg[base + t] : 0;
        int s = v;
#pragma unroll
        for (int o = 1; o < 32; o <<= 1){
            int n = __shfl_up_sync(0xffffffffu, s, o);
            if (lane >= o) s += n;
        }
        if (lane == 31) warpsum[wid] = s;
        __syncthreads();
        if (wid == 0){
            int ws = warpsum[lane];
            int t2 = ws;
#pragma unroll
            for (int o = 1; o < 32; o <<= 1){
                int n = __shfl_up_sync(0xffffffffu, t2, o);
                if (lane >= o) t2 += n;
            }
            warpoff[lane] = t2 - ws;
            if (lane == 31) warpsum[0] = t2;
        }
        __syncthreads();
        int tile_total = warpsum[0];
        if (base + t < NN){
            int ex = carry + warpoff[wid] + s - v;
            g_off[base + t] = ex;
            g_cursor[base + t] = ex;
        }
        __syncthreads();
        carry += tile_total;
    }
    if (t == 0) g_off[NN] = carry;
}

__global__ void k_scatter(const int* __restrict__ ei)
{
    int e = blockIdx.x*blockDim.x + threadIdx.x;
    if (e >= EE) return;
    int d = ei[EE + e];
    int pos = atomicAdd(&g_cursor[d], 1);
    g_csr[pos] = e;
}

// ---------------- warp-per-node fused attention, ONLINE SOFTMAX ----------------
__global__ void __launch_bounds__(256)
k_wnode(const int* __restrict__ ei, const float* __restrict__ ea,
        const float* __restrict__ lew, const float* __restrict__ att,
        const float* __restrict__ convb, const float* __restrict__ ng,
        const float* __restrict__ nb, float* __restrict__ alpha_out)
{
    __shared__ float4 s_cache[8][CAPW];   // logits per edge (4 heads)
    __shared__ int    s_csr  [8][CAPW];

    int w = threadIdx.x >> 5, lane = threadIdx.x & 31;
    int n = blockIdx.x*8 + w;
    if (n >= NN) return;

    int st = g_off[n];
    int deg = g_off[n+1] - st;
    int cbase = lane*8;
    int hsel = lane >> 3;

    float wa[8], l0[8], l1[8], l2[8];
#pragma unroll
    for (int j=0;j<8;j++){
        int c = cbase+j;
        wa[j] = att[c];
        l0[j] = lew[c*3+0]; l1[j] = lew[c*3+1]; l2[j] = lew[c*3+2];
    }
    float xr[8];
    {
        const float4* xr4 = (const float4*)(g_xr + (size_t)n*CC);
        float4 t0 = xr4[lane*2], t1 = xr4[lane*2+1];
        xr[0]=t0.x; xr[1]=t0.y; xr[2]=t0.z; xr[3]=t0.w;
        xr[4]=t1.x; xr[5]=t1.y; xr[6]=t1.z; xr[7]=t1.w;
    }

    for (int i=lane; i<deg && i<CAPW; i+=32) s_csr[w][i] = g_csr[st+i];
    __syncwarp();

    float mh = -INFINITY;
    float sh = 0.f;
    float acc[8] = {0.f,0.f,0.f,0.f,0.f,0.f,0.f,0.f};

    int i = 0;
    for (; i+1 < deg; i += 2){
        int eA = (i   < CAPW) ? s_csr[w][i]   : g_csr[st+i];
        int eB = (i+1 < CAPW) ? s_csr[w][i+1] : g_csr[st+i+1];
        int sA = ei[eA], sB = ei[eB];
        float r0A = ea[(size_t)eA*3+0], r1A = ea[(size_t)eA*3+1], ddA = ea[(size_t)eA*3+2];
        float r0B = ea[(size_t)eB*3+0], r1B = ea[(size_t)eB*3+1], ddB = ea[(size_t)eB*3+2];
        const float4* xlA = (const float4*)(g_xl + (size_t)sA*CC);
        const float4* xlB = (const float4*)(g_xl + (size_t)sB*CC);
        float4 a0A = xlA[lane*2], a1A = xlA[lane*2+1];
        float4 a0B = xlB[lane*2], a1B = xlB[lane*2+1];
        float xA[8] = { a0A.x,a0A.y,a0A.z,a0A.w, a1A.x,a1A.y,a1A.z,a1A.w };
        float xB[8] = { a0B.x,a0B.y,a0B.z,a0B.w, a1B.x,a1B.y,a1B.z,a1B.w };

        float pA = 0.f, pB = 0.f;
#pragma unroll
        for (int j=0;j<8;j++){
            float zA = xA[j] + xr[j] + r0A*l0[j] + r1A*l1[j] + ddA*l2[j];
            zA = (zA > 0.f) ? zA : 0.2f*zA;
            pA += zA * wa[j];
            float zB = xB[j] + xr[j] + r0B*l0[j] + r1B*l1[j] + ddB*l2[j];
            zB = (zB > 0.f) ? zB : 0.2f*zB;
            pB += zB * wa[j];
        }
#pragma unroll
        for (int o=4;o>0;o>>=1){
            pA += __shfl_xor_sync(0xffffffffu, pA, o);
            pB += __shfl_xor_sync(0xffffffffu, pB, o);
        }
        float hA = __shfl_sync(0xffffffffu, pA, hsel << 3);
        float hB = __shfl_sync(0xffffffffu, pB, hsel << 3);
        {
            float h0A = __shfl_sync(0xffffffffu, pA, 0),  h1A = __shfl_sync(0xffffffffu, pA, 8);
            float h2A = __shfl_sync(0xffffffffu, pA, 16), h3A = __shfl_sync(0xffffffffu, pA, 24);
            float h0B = __shfl_sync(0xffffffffu, pB, 0),  h1B = __shfl_sync(0xffffffffu, pB, 8);
            float h2B = __shfl_sync(0xffffffffu, pB, 16), h3B = __shfl_sync(0xffffffffu, pB, 24);
            if (lane < 4){
                float hv = (lane==0)?h0A:(lane==1)?h1A:(lane==2)?h2A:h3A;
                if (i < CAPW) ((float*)&s_cache[w][i])[lane] = hv;
                else          g_logits[(size_t)(st+i)*HH + lane] = hv;
            } else if (lane < 8){
                float hv = (lane==4)?h0B:(lane==5)?h1B:(lane==6)?h2B:h3B;
                if (i+1 < CAPW) ((float*)&s_cache[w][i+1])[lane-4] = hv;
                else            g_logits[(size_t)(st+i+1)*HH + (lane-4)] = hv;
            }
        }
        float mnew = fmaxf(mh, fmaxf(hA, hB));
        float scale = __expf(mh - mnew);
        float wAx = __expf(hA - mnew);
        float wBx = __expf(hB - mnew);
        sh = sh*scale + wAx + wBx;
#pragma unroll
        for (int j=0;j<8;j++)
            acc[j] = acc[j]*scale + wAx*xA[j] + wBx*xB[j];
        mh = mnew;
    }
    if (i < deg){
        int e = (i<CAPW) ? s_csr[w][i] : g_csr[st+i];
        int s = ei[e];
        float r0 = ea[(size_t)e*3+0], r1 = ea[(size_t)e*3+1], dd = ea[(size_t)e*3+2];
        const float4* xl4 = (const float4*)(g_xl + (size_t)s*CC);
        float4 a0 = xl4[lane*2], a1 = xl4[lane*2+1];
        float xA[8] = { a0.x,a0.y,a0.z,a0.w, a1.x,a1.y,a1.z,a1.w };
        float p = 0.f;
#pragma unroll
        for (int j=0;j<8;j++){
            float z = xA[j] + xr[j] + r0*l0[j] + r1*l1[j] + dd*l2[j];
            z = (z > 0.f) ? z : 0.2f*z;
            p += z * wa[j];
        }
#pragma unroll
        for (int o=4;o>0;o>>=1) p += __shfl_xor_sync(0xffffffffu, p, o);
        float hA = __shfl_sync(0xffffffffu, p, hsel << 3);
        {
            float h0 = __shfl_sync(0xffffffffu, p, 0),  h1 = __shfl_sync(0xffffffffu, p, 8);
            float h2 = __shfl_sync(0xffffffffu, p, 16), h3 = __shfl_sync(0xffffffffu, p, 24);
            if (lane < 4){
                float hv = (lane==0)?h0:(lane==1)?h1:(lane==2)?h2:h3;
                if (i < CAPW) ((float*)&s_cache[w][i])[lane] = hv;
                else          g_logits[(size_t)(st+i)*HH + lane] = hv;
            }
        }
        float mnew = fmaxf(mh, hA);
        float scale = __expf(mh - mnew);
        float wAx = __expf(hA - mnew);
        sh = sh*scale + wAx;
#pragma unroll
        for (int j=0;j<8;j++)
            acc[j] = acc[j]*scale + wAx*xA[j];
        mh = mnew;
    }
    __syncwarp();

    float fm0 = __shfl_sync(0xffffffffu, mh, 0),  fs0 = __shfl_sync(0xffffffffu, sh, 0);
    float fm1 = __shfl_sync(0xffffffffu, mh, 8),  fs1 = __shfl_sync(0xffffffffu, sh, 8);
    float fm2 = __shfl_sync(0xffffffffu, mh, 16), fs2 = __shfl_sync(0xffffffffu, sh, 16);
    float fm3 = __shfl_sync(0xffffffffu, mh, 24), fs3 = __shfl_sync(0xffffffffu, sh, 24);
    float is0 = 1.f/(fs0+1e-16f), is1 = 1.f/(fs1+1e-16f);
    float is2 = 1.f/(fs2+1e-16f), is3 = 1.f/(fs3+1e-16f);

    for (int k=lane; k<deg; k+=32){
        float4 lg = (k<CAPW) ? s_cache[w][k] : *(float4*)&g_logits[(size_t)(st+k)*HH];
        float4 al;
        al.x = __expf(lg.x - fm0)*is0; al.y = __expf(lg.y - fm1)*is1;
        al.z = __expf(lg.z - fm2)*is2; al.w = __expf(lg.w - fm3)*is3;
        int e = (k<CAPW) ? s_csr[w][k] : g_csr[st+k];
        *(float4*)&alpha_out[(size_t)e*HH] = al;
    }

    float inv = (hsel==0)?is0:(hsel==1)?is1:(hsel==2)?is2:is3;
    float v[8], part = 0.f;
#pragma unroll
    for (int j=0;j<8;j++){ v[j] = acc[j]*inv + convb[cbase+j]; part += v[j]; }
    float mean = wsum(part) * (1.f/256.f);
    float vp = 0.f;
#pragma unroll
    for (int j=0;j<8;j++){ v[j] -= mean; vp += v[j]*v[j]; }
    float var = wsum(vp) * (1.f/256.f);
    float rs = rsqrtf(var + 1e-5f);

    const float4* id4 = (const float4*)(g_ident + (size_t)n*CC);
    float4 d0 = id4[lane*2], d1 = id4[lane*2+1];
    float idv[8] = { d0.x,d0.y,d0.z,d0.w, d1.x,d1.y,d1.z,d1.w };
    float o[8];
#pragma unroll
    for (int j=0;j<8;j++){
        int c = cbase+j;
        float ov = v[j]*rs*ng[c] + nb[c];
        float tt = ov + idv[j];
        o[j] = rtf32(tt / (1.f + __expf(-tt)));
    }
    float4* pr4 = (float4*)(g_pre + (size_t)n*CC);
    pr4[lane*2]   = make_float4(o[0],o[1],o[2],o[3]);
    pr4[lane*2+1] = make_float4(o[4],o[5],o[6],o[7]);
}

// ---------------- launch ----------------
extern "C" void kernel_launch(void* const* d_in, const int* in_sizes, int n_in,
                              void* d_out, int out_size)
{
    const float* x        = (const float*)d_in[0];
    const float* kpts     = (const float*)d_in[1];
    const float* pts3d    = (const float*)d_in[2];
    const float* pe_w1    = (const float*)d_in[3];
    const float* pe_b1    = (const float*)d_in[4];
    const float* pe_g1    = (const float*)d_in[5];
    const float* pe_bn1   = (const float*)d_in[6];
    const float* pe_w2    = (const float*)d_in[7];
    const float* pe_b2    = (const float*)d_in[8];
    const float* pe_g2    = (const float*)d_in[9];
    const float* pe_bn2   = (const float*)d_in[10];
    const float* lin_l_w  = (const float*)d_in[11];
    const float* lin_l_b  = (const float*)d_in[12];
    const float* lin_r_w  = (const float*)d_in[13];
    const float* lin_r_b  = (const float*)d_in[14];
    const float* lin_edge = (const float*)d_in[15];
    const float* att      = (const float*)d_in[16];
    const float* conv_b   = (const float*)d_in[17];
    const float* norm_g   = (const float*)d_in[18];
    const float* norm_b   = (const float*)d_in[19];
    const float* res_w    = (const float*)d_in[20];
    const float* res_b    = (const float*)d_in[21];
    const float* proj_w   = (const float*)d_in[22];
    const float* proj_b   = (const float*)d_in[23];
    const int*   ei       = (const int*)d_in[24];

    float* out       = (float*)d_out;
    float* alpha_out = out + (size_t)NN*CC;          // [E,4]
    float* ea_out    = alpha_out + (size_t)EE*HH;    // [E,3]

    float *p_xcomb, *p_xl, *p_xr, *p_ident, *p_pre, *p_wr;
    cudaGetSymbolAddress((void**)&p_xcomb, g_xcomb);
    cudaGetSymbolAddress((void**)&p_xl,    g_xl);
    cudaGetSymbolAddress((void**)&p_xr,    g_xr);
    cudaGetSymbolAddress((void**)&p_ident, g_ident);
    cudaGetSymbolAddress((void**)&p_pre,   g_pre);
    cudaGetSymbolAddress((void**)&p_wr,    g_wr);

    cudaFuncSetAttribute(k_tcgemm2, cudaFuncAttributeMaxDynamicSharedMemorySize, GEMM_SMEM);

    // one-time side stream + events (created outside graph capture on the first
    // correctness call; reused — never destroyed during capture)
    static cudaStream_t s2 = nullptr;
    static cudaEvent_t  evFork = nullptr, evJoin = nullptr;
    if (s2 == nullptr){
        cudaStreamCreateWithFlags(&s2, cudaStreamNonBlocking);
        cudaEventCreateWithFlags(&evFork, cudaEventDisableTiming);
        cudaEventCreateWithFlags(&evJoin, cudaEventDisableTiming);
    }

    // ---- stage 0: nuv + deg init (both chains depend on this) ----
    k_nuv<<<(NN + 256)/256, 256>>>(kpts);
    cudaEventRecord(evFork, 0);

    // ---- side chain (stream s2): edge_attr -> scan -> scatter ----
    cudaStreamWaitEvent(s2, evFork, 0);
    k_edgeattr<<<(EE + 255)/256, 256, 0, s2>>>(ei, ea_out);
    k_scan<<<1, 1024, 0, s2>>>();
    k_scatter<<<(EE + 255)/256, 256, 0, s2>>>(ei);
    cudaEventRecord(evJoin, s2);

    // ---- main chain: pos encoder + node GEMMs ----
    k_prep<<<1, 256>>>(pe_w2);
    k_roundw<<<(CC*CC + 255)/256, 256>>>(lin_l_w, lin_r_w, res_w, proj_w);
    k_pos<<<(NN + 7)/8, 256>>>(x, kpts, pts3d,
                               pe_w1, pe_b1, pe_g1, pe_bn1,
                               pe_b2, pe_g2, pe_bn2);

    dim3 g3((NN + 127)/128, 6);
    k_tcgemm2<<<g3, 256, GEMM_SMEM>>>(p_xcomb, p_wr, 0,
                                      lin_l_b, lin_r_b, res_b,
                                      p_xl, p_xr, p_ident, NN);

    // ---- join, then fused edge phase + projector ----
    cudaStreamWaitEvent(0, evJoin, 0);
    k_wnode<<<(NN + 7)/8, 256>>>(ei, ea_out, lin_edge, att,
                                 conv_b, norm_g, norm_b, alpha_out);

    dim3 g1((NN + 127)/128, 2);
    k_tcgemm2<<<g1, 256, GEMM_SMEM>>>(p_pre, p_wr, 3,
                                      proj_b, proj_b, proj_b,
                                      out, out, out, NN);
}

// round 15
// speedup vs baseline: 1.4034x; 1.4034x over previous
#include <cuda_runtime.h>
#include <cuda_bf16.h>
#include <mma.h>
#include <math.h>
#include <cstdint>

using namespace nvcuda;

// Problem constants
#define NN 50000
#define EE 800000
#define HH 4
#define FF 64
#define CC 256   // H*F == CIN
#define CAPW 64  // per-warp cached degree; fallback to global beyond

// ---------------- device scratch (static, no allocation) ----------------
__device__ float    g_xcomb [(size_t)NN*CC];
__device__ float    g_xl    [(size_t)NN*CC];
__device__ float    g_xr    [(size_t)NN*CC];
__device__ float    g_ident [(size_t)NN*CC];
__device__ float    g_pre   [(size_t)NN*CC];
__device__ float    g_logits[(size_t)EE*HH];   // high-degree fallback (CSR-slot indexed)
__device__ float    g_nuv   [(size_t)NN*2];
__device__ float    g_w2t   [32*64];           // transposed pe_w2
__device__ float    g_wr    [4*CC*CC];         // tf32-rounded weights: lin_l, lin_r, res, proj
__device__ int      g_deg   [NN+1];
__device__ int      g_off   [NN+1];
__device__ int      g_cursor[NN+1];
__device__ int      g_csr   [EE];

// ---------------- helpers ----------------
__device__ __forceinline__ float wsum(float v){
#pragma unroll
    for (int o=16;o>0;o>>=1) v += __shfl_xor_sync(0xffffffffu, v, o);
    return v;
}

__device__ __forceinline__ float rtf32(float x){
    return wmma::__float_to_tf32(x);
}

__device__ __forceinline__ void cp_async16(unsigned int dst, const float* src, bool full){
    if (full)
        asm volatile("cp.async.cg.shared.global [%0], [%1], 16;" :: "r"(dst), "l"(src));
    else
        asm volatile("cp.async.cg.shared.global [%0], [%1], 16, 0;" :: "r"(dst), "l"(src));
}

// ---------------- kernels ----------------
// merged setup: deg zeroing + w2 transpose + weight tf32 rounding (one launch)
__global__ void k_setup(const float* __restrict__ w2,
                        const float* __restrict__ w0, const float* __restrict__ w1,
                        const float* __restrict__ wr2, const float* __restrict__ w3){
    int i = blockIdx.x*blockDim.x + threadIdx.x;
    if (i < NN+1) g_deg[i] = 0;
    if (i < 2048){
        int k = i >> 6, c = i & 63;
        g_w2t[i] = w2[c*32 + k];
    }
    if (i < CC*CC){
        g_wr[i]           = rtf32(w0[i]);
        g_wr[CC*CC + i]   = rtf32(w1[i]);
        g_wr[2*CC*CC + i] = rtf32(wr2[i]);
        g_wr[3*CC*CC + i] = rtf32(w3[i]);
    }
}

// positional encoder + build x_comb (tf32-rounded). One warp per node.
__global__ void k_pos(const float* __restrict__ x, const float* __restrict__ kpts,
                      const float* __restrict__ pts,
                      const float* __restrict__ w1, const float* __restrict__ b1,
                      const float* __restrict__ g1, const float* __restrict__ bn1,
                      const float* __restrict__ b2,
                      const float* __restrict__ g2, const float* __restrict__ bn2)
{
    int node = (blockIdx.x*blockDim.x + threadIdx.x) >> 5;
    int lane = threadIdx.x & 31;
    if (node >= NN) return;
    float u  = kpts[node*2+0] * (1.f/1216.f);
    float v  = kpts[node*2+1] * (1.f/352.f);
    float dep = fminf(fmaxf(pts[node*3+2], 0.1f), 100.f);
    if (lane == 0){ g_nuv[node*2]=u; g_nuv[node*2+1]=v; }

    float a = w1[lane*3+0]*u + w1[lane*3+1]*v + w1[lane*3+2]*dep + b1[lane];
    float m = wsum(a) * (1.f/32.f);
    float d0 = a - m;
    float var = wsum(d0*d0) * (1.f/32.f);
    float hn = d0 * rsqrtf(var + 1e-5f) * g1[lane] + bn1[lane];
    float h = hn / (1.f + expf(-hn));

    float acc0 = b2[lane], acc1 = b2[lane+32];
#pragma unroll
    for (int k=0;k<32;k++){
        float hk = __shfl_sync(0xffffffffu, h, k);
        acc0 += hk * g_w2t[k*64 + lane];
        acc1 += hk * g_w2t[k*64 + 32 + lane];
    }
    float m2 = wsum(acc0 + acc1) * (1.f/64.f);
    float e0 = acc0 - m2, e1 = acc1 - m2;
    float var2 = wsum(e0*e0 + e1*e1) * (1.f/64.f);
    float rs = rsqrtf(var2 + 1e-5f);
    float p0 = e0*rs*g2[lane]    + bn2[lane];
    float p1 = e1*rs*g2[lane+32] + bn2[lane+32];

    size_t base = (size_t)node * CC;
    g_xcomb[base + 192 + lane] = rtf32(p0);
    g_xcomb[base + 224 + lane] = rtf32(p1);
#pragma unroll
    for (int j=lane; j<192; j+=32) g_xcomb[base + j] = rtf32(x[(size_t)node*192 + j]);
}

// ---------------- tf32 tensor-core GEMM, 128x128 tile, cp.async 2-stage ----------------
#define SS (128*40)                 // floats per matrix per stage
#define GEMM_SMEM (2*2*SS*4)        // 81920 B (also covers Cs 128*136*4 = 69632)

__global__ void __launch_bounds__(256, 2)
k_tcgemm2(const float* __restrict__ A,
          const float* __restrict__ Wbase, int tgt0,
          const float* __restrict__ b0, const float* __restrict__ b1,
          const float* __restrict__ b2,
          float* __restrict__ C0, float* __restrict__ C1,
          float* __restrict__ C2, int M)
{
    extern __shared__ float sm[];

    int t  = threadIdx.x;
    int m0 = blockIdx.x * 128;
    int tgt = blockIdx.y >> 1;
    int c0  = (blockIdx.y & 1) * 128;

    const float* W    = Wbase + (size_t)(tgt0 + tgt)*CC*CC;
    const float* bias = (tgt == 0) ? b0 : (tgt == 1) ? b1 : b2;
    float*       C    = (tgt == 0) ? C0 : (tgt == 1) ? C1 : C2;

    int warp = t >> 5;
    int r  = (warp & 3) * 32;
    int cb = (warp >> 2) * 64;

    unsigned int smb = (unsigned int)__cvta_generic_to_shared(sm);

    int rows[4], cols[4];
#pragma unroll
    for (int j=0;j<4;j++){
        int id = t + j*256;
        rows[j] = id >> 3;
        cols[j] = (id & 7) * 4;
    }

    wmma::fragment<wmma::accumulator, 16, 16, 8, float> acc[2][4];
#pragma unroll
    for (int i=0;i<2;i++)
#pragma unroll
        for (int j=0;j<4;j++) wmma::fill_fragment(acc[i][j], 0.f);

    auto issue = [&](int k0, int s){
#pragma unroll
        for (int j=0;j<4;j++){
            int row = rows[j], col = cols[j];
            bool vA = (m0 + row < M);
            const float* srcA = &A[(size_t)((vA ? m0 + row : 0)) * CC + k0 + col];
            cp_async16(smb + (unsigned int)((s*2*SS + row*40 + col)*4), srcA, vA);
            const float* srcW = &W[(size_t)(c0 + row) * CC + k0 + col];
            cp_async16(smb + (unsigned int)((s*2*SS + SS + row*40 + col)*4), srcW, true);
        }
        asm volatile("cp.async.commit_group;" ::: "memory");
    };

    issue(0, 0);

    for (int it = 0; it < 8; ++it){
        int s = it & 1;
        if (it < 7) issue((it+1)*32, s^1);
        if (it < 7) asm volatile("cp.async.wait_group 1;" ::: "memory");
        else        asm volatile("cp.async.wait_group 0;" ::: "memory");
        __syncthreads();

        float* As = sm + s*2*SS;
        float* Ws = As + SS;
#pragma unroll
        for (int kk = 0; kk < 32; kk += 8){
            wmma::fragment<wmma::matrix_a, 16, 16, 8, wmma::precision::tf32, wmma::row_major> af[2];
            wmma::fragment<wmma::matrix_b, 16, 16, 8, wmma::precision::tf32, wmma::col_major> bf[4];
#pragma unroll
            for (int i = 0; i < 2; i++)
                wmma::load_matrix_sync(af[i], &As[(r + 16*i)*40 + kk], 40);
#pragma unroll
            for (int j = 0; j < 4; j++)
                wmma::load_matrix_sync(bf[j], &Ws[(cb + 16*j)*40 + kk], 40);
#pragma unroll
            for (int i = 0; i < 2; i++)
#pragma unroll
                for (int j = 0; j < 4; j++)
                    wmma::mma_sync(acc[i][j], af[i], bf[j], acc[i][j]);
        }
        __syncthreads();
    }

    float* Cs = sm;  // [128][136] aliases both stages
#pragma unroll
    for (int i = 0; i < 2; i++)
#pragma unroll
        for (int j = 0; j < 4; j++)
            wmma::store_matrix_sync(&Cs[(r + 16*i)*136 + cb + 16*j], acc[i][j], 136, wmma::mem_row_major);
    __syncthreads();

    int col4 = (t & 31) * 4;
    int rb   = t >> 5;
    float4 bv = *(const float4*)&bias[c0 + col4];
#pragma unroll
    for (int i = 0; i < 16; i++){
        int row = rb + i * 8;
        int m = m0 + row;
        if (m < M){
            float4 v = *(float4*)&Cs[row*136 + col4];
            v.x += bv.x; v.y += bv.y; v.z += bv.z; v.w += bv.w;
            *(float4*)&C[(size_t)m * CC + c0 + col4] = v;
        }
    }
}

// edge_attr output + degree histogram
__global__ void k_edgeattr(const int* __restrict__ ei, float* __restrict__ ea)
{
    int e = blockIdx.x*blockDim.x + threadIdx.x;
    if (e >= EE) return;
    int s = ei[e], d = ei[EE + e];
    float r0 = g_nuv[d*2+0] - g_nuv[s*2+0];
    float r1 = g_nuv[d*2+1] - g_nuv[s*2+1];
    float dist = sqrtf(r0*r0 + r1*r1);
    ea[(size_t)e*3+0] = r0;
    ea[(size_t)e*3+1] = r1;
    ea[(size_t)e*3+2] = dist;
    atomicAdd(&g_deg[d], 1);
}

// single-block exclusive scan of degrees -> offsets (+cursor copy)
__global__ void k_scan()
{
    __shared__ int warpsum[32];
    __shared__ int warpoff[32];
    int t = threadIdx.x;
    int lane = t & 31, wid = t >> 5;
    int carry = 0;
    for (int base = 0; base < NN; base += 1024){
        int v = (base + t < NN) ? g_deg[base + t] : 0;
        int s = v;
#pragma unroll
        for (int o = 1; o < 32; o <<= 1){
            int n = __shfl_up_sync(0xffffffffu, s, o);
            if (lane >= o) s += n;
        }
        if (lane == 31) warpsum[wid] = s;
        __syncthreads();
        if (wid == 0){
            int ws = warpsum[lane];
            int t2 = ws;
#pragma unroll
            for (int o = 1; o < 32; o <<= 1){
                int n = __shfl_up_sync(0xffffffffu, t2, o);
                if (lane >= o) t2 += n;
            }
            warpoff[lane] = t2 - ws;
            if (lane == 31) warpsum[0] = t2;
        }
        __syncthreads();
        int tile_total = warpsum[0];
        if (base + t < NN){
            int ex = carry + warpoff[wid] + s - v;
            g_off[base + t] = ex;
            g_cursor[base + t] = ex;
        }
        __syncthreads();
        carry += tile_total;
    }
    if (t == 0) g_off[NN] = carry;
}

__global__ void k_scatter(const int* __restrict__ ei)
{
    int e = blockIdx.x*blockDim.x + threadIdx.x;
    if (e >= EE) return;
    int d = ei[EE + e];
    int pos = atomicAdd(&g_cursor[d], 1);
    g_csr[pos] = e;
}

// ---------------- warp-per-node fused attention, ONLINE SOFTMAX ----------------
__global__ void __launch_bounds__(256)
k_wnode(const int* __restrict__ ei, const float* __restrict__ ea,
        const float* __restrict__ lew, const float* __restrict__ att,
        const float* __restrict__ convb, const float* __restrict__ ng,
        const float* __restrict__ nb, float* __restrict__ alpha_out)
{
    __shared__ float4 s_cache[8][CAPW];   // logits per edge (4 heads)
    __shared__ int    s_csr  [8][CAPW];

    int w = threadIdx.x >> 5, lane = threadIdx.x & 31;
    int n = blockIdx.x*8 + w;
    if (n >= NN) return;

    int st = g_off[n];
    int deg = g_off[n+1] - st;
    int cbase = lane*8;
    int hsel = lane >> 3;

    float wa[8], l0[8], l1[8], l2[8];
#pragma unroll
    for (int j=0;j<8;j++){
        int c = cbase+j;
        wa[j] = att[c];
        l0[j] = lew[c*3+0]; l1[j] = lew[c*3+1]; l2[j] = lew[c*3+2];
    }
    float xr[8];
    {
        const float4* xr4 = (const float4*)(g_xr + (size_t)n*CC);
        float4 t0 = xr4[lane*2], t1 = xr4[lane*2+1];
        xr[0]=t0.x; xr[1]=t0.y; xr[2]=t0.z; xr[3]=t0.w;
        xr[4]=t1.x; xr[5]=t1.y; xr[6]=t1.z; xr[7]=t1.w;
    }

    for (int i=lane; i<deg && i<CAPW; i+=32) s_csr[w][i] = g_csr[st+i];
    __syncwarp();

    float mh = -INFINITY;
    float sh = 0.f;
    float acc[8] = {0.f,0.f,0.f,0.f,0.f,0.f,0.f,0.f};

    int i = 0;
    for (; i+1 < deg; i += 2){
        int eA = (i   < CAPW) ? s_csr[w][i]   : g_csr[st+i];
        int eB = (i+1 < CAPW) ? s_csr[w][i+1] : g_csr[st+i+1];
        int sA = ei[eA], sB = ei[eB];
        float r0A = ea[(size_t)eA*3+0], r1A = ea[(size_t)eA*3+1], ddA = ea[(size_t)eA*3+2];
        float r0B = ea[(size_t)eB*3+0], r1B = ea[(size_t)eB*3+1], ddB = ea[(size_t)eB*3+2];
        const float4* xlA = (const float4*)(g_xl + (size_t)sA*CC);
        const float4* xlB = (const float4*)(g_xl + (size_t)sB*CC);
        float4 a0A = xlA[lane*2], a1A = xlA[lane*2+1];
        float4 a0B = xlB[lane*2], a1B = xlB[lane*2+1];
        float xA[8] = { a0A.x,a0A.y,a0A.z,a0A.w, a1A.x,a1A.y,a1A.z,a1A.w };
        float xB[8] = { a0B.x,a0B.y,a0B.z,a0B.w, a1B.x,a1B.y,a1B.z,a1B.w };

        float pA = 0.f, pB = 0.f;
#pragma unroll
        for (int j=0;j<8;j++){
            float zA = xA[j] + xr[j] + r0A*l0[j] + r1A*l1[j] + ddA*l2[j];
            zA = (zA > 0.f) ? zA : 0.2f*zA;
            pA += zA * wa[j];
            float zB = xB[j] + xr[j] + r0B*l0[j] + r1B*l1[j] + ddB*l2[j];
            zB = (zB > 0.f) ? zB : 0.2f*zB;
            pB += zB * wa[j];
        }
#pragma unroll
        for (int o=4;o>0;o>>=1){
            pA += __shfl_xor_sync(0xffffffffu, pA, o);
            pB += __shfl_xor_sync(0xffffffffu, pB, o);
        }
        float hA = __shfl_sync(0xffffffffu, pA, hsel << 3);
        float hB = __shfl_sync(0xffffffffu, pB, hsel << 3);
        {
            float h0A = __shfl_sync(0xffffffffu, pA, 0),  h1A = __shfl_sync(0xffffffffu, pA, 8);
            float h2A = __shfl_sync(0xffffffffu, pA, 16), h3A = __shfl_sync(0xffffffffu, pA, 24);
            float h0B = __shfl_sync(0xffffffffu, pB, 0),  h1B = __shfl_sync(0xffffffffu, pB, 8);
            float h2B = __shfl_sync(0xffffffffu, pB, 16), h3B = __shfl_sync(0xffffffffu, pB, 24);
            if (lane < 4){
                float hv = (lane==0)?h0A:(lane==1)?h1A:(lane==2)?h2A:h3A;
                if (i < CAPW) ((float*)&s_cache[w][i])[lane] = hv;
                else          g_logits[(size_t)(st+i)*HH + lane] = hv;
            } else if (lane < 8){
                float hv = (lane==4)?h0B:(lane==5)?h1B:(lane==6)?h2B:h3B;
                if (i+1 < CAPW) ((float*)&s_cache[w][i+1])[lane-4] = hv;
                else            g_logits[(size_t)(st+i+1)*HH + (lane-4)] = hv;
            }
        }
        float mnew = fmaxf(mh, fmaxf(hA, hB));
        float scale = __expf(mh - mnew);
        float wAx = __expf(hA - mnew);
        float wBx = __expf(hB - mnew);
        sh = sh*scale + wAx + wBx;
#pragma unroll
        for (int j=0;j<8;j++)
            acc[j] = acc[j]*scale + wAx*xA[j] + wBx*xB[j];
        mh = mnew;
    }
    if (i < deg){
        int e = (i<CAPW) ? s_csr[w][i] : g_csr[st+i];
        int s = ei[e];
        float r0 = ea[(size_t)e*3+0], r1 = ea[(size_t)e*3+1], dd = ea[(size_t)e*3+2];
        const float4* xl4 = (const float4*)(g_xl + (size_t)s*CC);
        float4 a0 = xl4[lane*2], a1 = xl4[lane*2+1];
        float xA[8] = { a0.x,a0.y,a0.z,a0.w, a1.x,a1.y,a1.z,a1.w };
        float p = 0.f;
#pragma unroll
        for (int j=0;j<8;j++){
            float z = xA[j] + xr[j] + r0*l0[j] + r1*l1[j] + dd*l2[j];
            z = (z > 0.f) ? z : 0.2f*z;
            p += z * wa[j];
        }
#pragma unroll
        for (int o=4;o>0;o>>=1) p += __shfl_xor_sync(0xffffffffu, p, o);
        float hA = __shfl_sync(0xffffffffu, p, hsel << 3);
        {
            float h0 = __shfl_sync(0xffffffffu, p, 0),  h1 = __shfl_sync(0xffffffffu, p, 8);
            float h2 = __shfl_sync(0xffffffffu, p, 16), h3 = __shfl_sync(0xffffffffu, p, 24);
            if (lane < 4){
                float hv = (lane==0)?h0:(lane==1)?h1:(lane==2)?h2:h3;
                if (i < CAPW) ((float*)&s_cache[w][i])[lane] = hv;
                else          g_logits[(size_t)(st+i)*HH + lane] = hv;
            }
        }
        float mnew = fmaxf(mh, hA);
        float scale = __expf(mh - mnew);
        float wAx = __expf(hA - mnew);
        sh = sh*scale + wAx;
#pragma unroll
        for (int j=0;j<8;j++)
            acc[j] = acc[j]*scale + wAx*xA[j];
        mh = mnew;
    }
    __syncwarp();

    float fm0 = __shfl_sync(0xffffffffu, mh, 0),  fs0 = __shfl_sync(0xffffffffu, sh, 0);
    float fm1 = __shfl_sync(0xffffffffu, mh, 8),  fs1 = __shfl_sync(0xffffffffu, sh, 8);
    float fm2 = __shfl_sync(0xffffffffu, mh, 16), fs2 = __shfl_sync(0xffffffffu, sh, 16);
    float fm3 = __shfl_sync(0xffffffffu, mh, 24), fs3 = __shfl_sync(0xffffffffu, sh, 24);
    float is0 = 1.f/(fs0+1e-16f), is1 = 1.f/(fs1+1e-16f);
    float is2 = 1.f/(fs2+1e-16f), is3 = 1.f/(fs3+1e-16f);

    for (int k=lane; k<deg; k+=32){
        float4 lg = (k<CAPW) ? s_cache[w][k] : *(float4*)&g_logits[(size_t)(st+k)*HH];
        float4 al;
        al.x = __expf(lg.x - fm0)*is0; al.y = __expf(lg.y - fm1)*is1;
        al.z = __expf(lg.z - fm2)*is2; al.w = __expf(lg.w - fm3)*is3;
        int e = (k<CAPW) ? s_csr[w][k] : g_csr[st+k];
        *(float4*)&alpha_out[(size_t)e*HH] = al;
    }

    float inv = (hsel==0)?is0:(hsel==1)?is1:(hsel==2)?is2:is3;
    float v[8], part = 0.f;
#pragma unroll
    for (int j=0;j<8;j++){ v[j] = acc[j]*inv + convb[cbase+j]; part += v[j]; }
    float mean = wsum(part) * (1.f/256.f);
    float vp = 0.f;
#pragma unroll
    for (int j=0;j<8;j++){ v[j] -= mean; vp += v[j]*v[j]; }
    float var = wsum(vp) * (1.f/256.f);
    float rs = rsqrtf(var + 1e-5f);

    const float4* id4 = (const float4*)(g_ident + (size_t)n*CC);
    float4 d0 = id4[lane*2], d1 = id4[lane*2+1];
    float idv[8] = { d0.x,d0.y,d0.z,d0.w, d1.x,d1.y,d1.z,d1.w };
    float o[8];
#pragma unroll
    for (int j=0;j<8;j++){
        int c = cbase+j;
        float ov = v[j]*rs*ng[c] + nb[c];
        float tt = ov + idv[j];
        o[j] = rtf32(tt / (1.f + __expf(-tt)));
    }
    float4* pr4 = (float4*)(g_pre + (size_t)n*CC);
    pr4[lane*2]   = make_float4(o[0],o[1],o[2],o[3]);
    pr4[lane*2+1] = make_float4(o[4],o[5],o[6],o[7]);
}

// ---------------- launch ----------------
extern "C" void kernel_launch(void* const* d_in, const int* in_sizes, int n_in,
                              void* d_out, int out_size)
{
    const float* x        = (const float*)d_in[0];
    const float* kpts     = (const float*)d_in[1];
    const float* pts3d    = (const float*)d_in[2];
    const float* pe_w1    = (const float*)d_in[3];
    const float* pe_b1    = (const float*)d_in[4];
    const float* pe_g1    = (const float*)d_in[5];
    const float* pe_bn1   = (const float*)d_in[6];
    const float* pe_w2    = (const float*)d_in[7];
    const float* pe_b2    = (const float*)d_in[8];
    const float* pe_g2    = (const float*)d_in[9];
    const float* pe_bn2   = (const float*)d_in[10];
    const float* lin_l_w  = (const float*)d_in[11];
    const float* lin_l_b  = (const float*)d_in[12];
    const float* lin_r_w  = (const float*)d_in[13];
    const float* lin_r_b  = (const float*)d_in[14];
    const float* lin_edge = (const float*)d_in[15];
    const float* att      = (const float*)d_in[16];
    const float* conv_b   = (const float*)d_in[17];
    const float* norm_g   = (const float*)d_in[18];
    const float* norm_b   = (const float*)d_in[19];
    const float* res_w    = (const float*)d_in[20];
    const float* res_b    = (const float*)d_in[21];
    const float* proj_w   = (const float*)d_in[22];
    const float* proj_b   = (const float*)d_in[23];
    const int*   ei       = (const int*)d_in[24];

    float* out       = (float*)d_out;
    float* alpha_out = out + (size_t)NN*CC;          // [E,4]
    float* ea_out    = alpha_out + (size_t)EE*HH;    // [E,3]

    float *p_xcomb, *p_xl, *p_xr, *p_ident, *p_pre, *p_wr;
    cudaGetSymbolAddress((void**)&p_xcomb, g_xcomb);
    cudaGetSymbolAddress((void**)&p_xl,    g_xl);
    cudaGetSymbolAddress((void**)&p_xr,    g_xr);
    cudaGetSymbolAddress((void**)&p_ident, g_ident);
    cudaGetSymbolAddress((void**)&p_pre,   g_pre);
    cudaGetSymbolAddress((void**)&p_wr,    g_wr);

    cudaFuncSetAttribute(k_tcgemm2, cudaFuncAttributeMaxDynamicSharedMemorySize, GEMM_SMEM);

    // merged init/transpose/round (covers 65536 >= CC*CC and NN+1 and 2048)
    k_setup<<<(CC*CC + 255)/256, 256>>>(pe_w2, lin_l_w, lin_r_w, res_w, proj_w);
    k_pos<<<(NN + 7)/8, 256>>>(x, kpts, pts3d,
                               pe_w1, pe_b1, pe_g1, pe_bn1,
                               pe_b2, pe_g2, pe_bn2);

    // fused lin_l + lin_r + res GEMMs (tf32, 128x128 tiles, cp.async pipelined)
    dim3 g3((NN + 127)/128, 6);
    k_tcgemm2<<<g3, 256, GEMM_SMEM>>>(p_xcomb, p_wr, 0,
                                      lin_l_b, lin_r_b, res_b,
                                      p_xl, p_xr, p_ident, NN);

    k_edgeattr<<<(EE + 255)/256, 256>>>(ei, ea_out);
    k_scan<<<1, 1024>>>();
    k_scatter<<<(EE + 255)/256, 256>>>(ei);

    // fused edge phase (online softmax, single xl-gather pass)
    k_wnode<<<(NN + 7)/8, 256>>>(ei, ea_out, lin_edge, att,
                                 conv_b, norm_g, norm_b, alpha_out);

    // projector GEMM
    dim3 g1((NN + 127)/128, 2);
    k_tcgemm2<<<g1, 256, GEMM_SMEM>>>(p_pre, p_wr, 3,
                                      proj_b, proj_b, proj_b,
                                      out, out, out, NN);
}